// round 14
// baseline (speedup 1.0000x reference)
#include <cuda_runtime.h>
#include <cooperative_groups.h>
#include <cstdint>

#define BB 8
#define HH 256
#define WW 256
#define NPIX (BB*HH*WW)
#define N_ITERS 200
#define TT 4                 // halo width / sub-iterations per exchange
#define NB (N_ITERS/TT)      // 50 exchange rounds (49 barriers)
#define NCTAS 128            // 8 images * (4x4) 64x64 tiles, 1 CTA/SM (balanced)
#define NTHREADS 672         // 21 warps; 648 active (36 col-pairs x 18 row groups)
#define NACT 648
#define NGRP 18
#define RPT 4                // rows per thread (x2 cols = 8 cells)
#define EXT 72               // ext region 72x72 (tile 64 + 2*TT)

// Double-buffered full-state exchange arrays (alloc-free scratch)
__device__ float gU [2][NPIX];
__device__ float gUB[2][NPIX];
__device__ float gP [2][NPIX];
__device__ float gQ [2][NPIX];

// Per-image barrier counters, one 128B line each (zero-initialized).
struct __align__(128) ImgLine { unsigned long long v; unsigned long long pad[15]; };
__device__ ImgLine g_arr[BB];

__device__ __forceinline__ float clipf(float v, float b) {
    return fminf(fmaxf(v, -b), b);
}
__device__ __forceinline__ float ldcg(const float* p) {
    float v;
    asm volatile("ld.global.cg.f32 %0, [%1];" : "=f"(v) : "l"(p) : "memory");
    return v;
}
__device__ __forceinline__ unsigned long long ld_acq(const unsigned long long* p) {
    unsigned long long v;
    asm volatile("ld.acquire.gpu.global.u64 %0, [%1];" : "=l"(v) : "l"(p) : "memory");
    return v;
}
__device__ __forceinline__ void red_rel_add1(unsigned long long* p) {
    asm volatile("red.release.gpu.global.add.u64 [%0], %1;" :: "l"(p), "l"(1ULL) : "memory");
}

__global__ __launch_bounds__(NTHREADS, 1)
void tv_block(const float* __restrict__ f,
              const float* __restrict__ lam,
              float* __restrict__ out)
{
    const float SIG  = 0.35355339f;
    const float TAUc = 0.35355339f;
    const float INV  = 1.0f / (1.0f + TAUc);

    // Cross-thread arrays (only what neighbors actually read):
    __shared__ float ubE[EXT][37];       // ub of even ext col 2cp at [r][cp]; pad cp=36
    __shared__ float qO [EXT][38];       // q of odd ext col 2cp+1 at [r][cp+1]; pad [r][0]
    __shared__ float ubB[NGRP + 1][EXT]; // first-row ub of each row group; pad rg=NGRP
    __shared__ float pB [NGRP + 1][EXT]; // last-row p of group at [rg+1][c]; pad [0]

    const int cta = blockIdx.x;
    const int img = cta >> 4;
    const int t   = cta & 15;
    const int i0  = (t >> 2) * 64;
    const int j0  = (t & 3) * 64;
    const int tid = threadIdx.x;
    const bool act = (tid < NACT);
    const int cp  = tid % 36;          // column pair 0..35
    const int rg  = tid / 36;          // row group 0..17 (>=18 inactive)
    const int rb  = rg * RPT;          // first ext row of my strip
    const int c0  = 2 * cp;            // my even ext col

    const int gi_top = i0 - TT + rb;
    const int gj0    = j0 - TT + c0;
    const int base   = (img * HH + gi_top) * WW + gj0;  // cell (k,e) at base+k*WW+e

    // Barrier epoch (monotone; exact multiple at entry since launches drain).
    unsigned long long epoch = 0;
    if (tid == 0) epoch = *(volatile unsigned long long*)&g_arr[img].v;

    // Zero all SMEM (pads stay 0 = finite garbage for ring math)
    for (int x = tid; x < EXT * 37;        x += NTHREADS) ((float*)ubE)[x] = 0.f;
    for (int x = tid; x < EXT * 38;        x += NTHREADS) ((float*)qO )[x] = 0.f;
    for (int x = tid; x < (NGRP+1) * EXT;  x += NTHREADS) ((float*)ubB)[x] = 0.f;
    for (int x = tid; x < (NGRP+1) * EXT;  x += NTHREADS) ((float*)pB )[x] = 0.f;

    // ---- per-cell state in registers (n = 2k+e) ----
    float u[8], ub[8], p[8], q[8], fv[8], lx[8], ly[8];
    if (act) {
#pragma unroll
        for (int k = 0; k < RPT; k++) {
#pragma unroll
            for (int e = 0; e < 2; e++) {
                const int n  = 2 * k + e;
                const int gi = gi_top + k, gj = gj0 + e;
                const bool ii = (gi >= 0 && gi < HH && gj >= 0 && gj < WW);
                const int idx = base + k * WW + e;
                const float fk = ii ? f[idx] : 0.f;
                fv[n] = fk; u[n] = fk; ub[n] = fk; p[n] = 0.f; q[n] = 0.f;
                lx[n] = (ii && gi < HH - 1) ? lam[idx + WW] : 0.f;  // bound p(r,c)
                ly[n] = (ii && gj < WW - 1) ? lam[idx + 1]  : 0.f;  // bound q(r,c)
            }
        }
    }
    __syncthreads();   // zeros complete before targeted writes
    if (act) {
#pragma unroll
        for (int k = 0; k < RPT; k++) ubE[rb + k][cp] = ub[2 * k];
        ubB[rg][c0] = ub[0]; ubB[rg][c0 + 1] = ub[1];
    }
    __syncthreads();

#pragma unroll 1
    for (int blk = 0; blk < NB; blk++) {
        if (blk) {
            const int sb = blk & 1;
            // ---- publish interior frame (width-TT border of the true tile) ----
            if (act) {
#pragma unroll
                for (int k = 0; k < RPT; k++) {
#pragma unroll
                    for (int e = 0; e < 2; e++) {
                        const int n = 2 * k + e, r = rb + k, c = c0 + e;
                        const bool interior = (r >= TT && r < EXT - TT &&
                                               c >= TT && c < EXT - TT);
                        if (interior && (r < 2*TT || r >= EXT - 2*TT ||
                                         c < 2*TT || c >= EXT - 2*TT)) {
                            const int idx = base + k * WW + e;
                            gU [sb][idx] = u[n];  gUB[sb][idx] = ub[n];
                            gP [sb][idx] = p[n];  gQ [sb][idx] = q[n];
                        }
                    }
                }
            }
            __syncthreads();   // all publishes of this CTA complete

            // ---- per-image 16-CTA barrier (arrive + spin, monotone) ----
            if (tid == 0) {
                red_rel_add1(&g_arr[img].v);
                const unsigned long long tgt =
                    epoch + 16ULL * (unsigned long long)blk;
                while ((long long)(ld_acq(&g_arr[img].v) - tgt) < 0) { }
            }
            __syncthreads();   // release observed; ring reads ordered

            // ---- refresh ring (full state) from neighbors' publishes ----
            if (act) {
#pragma unroll
                for (int k = 0; k < RPT; k++) {
#pragma unroll
                    for (int e = 0; e < 2; e++) {
                        const int n = 2 * k + e, r = rb + k, c = c0 + e;
                        const int gi = gi_top + k, gj = gj0 + e;
                        const bool ring = (r < TT || r >= EXT - TT ||
                                           c < TT || c >= EXT - TT);
                        if (ring && gi >= 0 && gi < HH && gj >= 0 && gj < WW) {
                            const int idx = base + k * WW + e;
                            u[n]  = ldcg(&gU [sb][idx]);
                            ub[n] = ldcg(&gUB[sb][idx]);
                            p[n]  = ldcg(&gP [sb][idx]);
                            q[n]  = ldcg(&gQ [sb][idx]);
                            if (e == 0) ubE[r][cp] = ub[n];
                            if (k == 0) ubB[rg][c] = ub[n];
                        }
                    }
                }
            }
            __syncthreads();
        }

#pragma unroll 1
        for (int s = 0; s < TT; s++) {
            // ---- phase 1: dual update (p, q) ----
            if (act) {
                const float ubb0 = ubB[rg + 1][c0];
                const float ubb1 = ubB[rg + 1][c0 + 1];
#pragma unroll
                for (int k = 0; k < RPT; k++) {
                    const int r = rb + k;
                    {   // even column: ub_right is own register ub[n+1]
                        const int n = 2 * k;
                        const float ub_b = (k < RPT - 1) ? ub[n + 2] : ubb0;
                        p[n] = clipf(p[n] + SIG * (ub_b     - ub[n]), lx[n]);
                        q[n] = clipf(q[n] + SIG * (ub[n + 1] - ub[n]), ly[n]);
                    }
                    {   // odd column: ub_right from right thread's even col
                        const int n = 2 * k + 1;
                        const float ub_b = (k < RPT - 1) ? ub[n + 2] : ubb1;
                        const float ub_r = ubE[r][cp + 1];
                        p[n] = clipf(p[n] + SIG * (ub_b - ub[n]), lx[n]);
                        q[n] = clipf(q[n] + SIG * (ub_r - ub[n]), ly[n]);
                        qO[r][cp + 1] = q[n];
                    }
                }
                pB[rg + 1][c0]     = p[2 * (RPT - 1)];
                pB[rg + 1][c0 + 1] = p[2 * (RPT - 1) + 1];
            }
            __syncthreads();

            // ---- phase 2: primal update (u, ubar) ----
            if (act) {
                float pu0 = pB[rg][c0];
                float pu1 = pB[rg][c0 + 1];
#pragma unroll
                for (int k = 0; k < RPT; k++) {
                    const int r = rb + k;
                    const float qw = qO[r][cp];   // q(r, c0-1) from left thread
                    {   // even column
                        const int n = 2 * k;
                        const float div = (pu0 - p[n]) + (qw - q[n]);
                        const float un  = (u[n] + TAUc * (fv[n] - div)) * INV;
                        ub[n] = 2.f * un - u[n];  u[n] = un;  pu0 = p[n];
                        ubE[r][cp] = ub[n];
                    }
                    {   // odd column: q_left is own register q[n-1]
                        const int n = 2 * k + 1;
                        const float div = (pu1 - p[n]) + (q[n - 1] - q[n]);
                        const float un  = (u[n] + TAUc * (fv[n] - div)) * INV;
                        ub[n] = 2.f * un - u[n];  u[n] = un;  pu1 = p[n];
                    }
                }
                ubB[rg][c0] = ub[0];  ubB[rg][c0 + 1] = ub[1];
            }
            __syncthreads();
        }
    }

    // ---- write interior result ----
    if (act) {
#pragma unroll
        for (int k = 0; k < RPT; k++) {
#pragma unroll
            for (int e = 0; e < 2; e++) {
                const int r = rb + k, c = c0 + e;
                if (r >= TT && r < EXT - TT && c >= TT && c < EXT - TT)
                    out[base + k * WW + e] = u[2 * k + e];
            }
        }
    }
}

extern "C" void kernel_launch(void* const* d_in, const int* in_sizes, int n_in,
                              void* d_out, int out_size) {
    const float* f   = (const float*)d_in[0];
    const float* lam = (const float*)d_in[1];
    float* out = (float*)d_out;

    // Cooperative launch only for co-residency (per-image barrier needs all
    // 16 CTAs of an image resident); no grid.sync used.
    void* args[] = { (void*)&f, (void*)&lam, (void*)&out };
    cudaLaunchCooperativeKernel((void*)tv_block,
                                dim3(NCTAS), dim3(NTHREADS),
                                args, 0, 0);
}